// round 3
// baseline (speedup 1.0000x reference)
#include <cuda_runtime.h>
#include <cstdint>

// Problem constants (GATv2: N=100000, E=1600000, D_IN=128, H=4, C=32)
#define NMAX 100000
#define EMAX 1600000
#define NEG_SLOPE 0.2f

// Scratch (allocation-free: __device__ globals)
__device__ float g_xl[(size_t)NMAX * 128];   // 51.2 MB  x @ W_l
__device__ float g_xr[(size_t)NMAX * 128];   // 51.2 MB  x @ W_r
__device__ float g_ex[(size_t)EMAX * 4];     // 25.6 MB  exp(score) per edge/head
__device__ float g_den[(size_t)NMAX * 4];    //  1.6 MB  softmax denominator per node/head

// ---------------------------------------------------------------------------
// K0: init out = bias (out is poisoned each run) and zero denominators
// ---------------------------------------------------------------------------
__global__ void k_init(float* __restrict__ out, const float* __restrict__ bias, int n) {
    int i = blockIdx.x * blockDim.x + threadIdx.x;
    int tot = n * 128;
    if (i < tot) out[i] = bias[i & 127];
    if (i < n * 4) g_den[i] = 0.f;
}

// ---------------------------------------------------------------------------
// K1: fused GEMM  xl = x @ W_l, xr = x @ W_r   (both [N,128] = x[N,128] @ W[128,128])
// Block: 64 rows x 256 output cols (128 xl | 128 xr). 256 threads,
// each thread computes a 4x16 microtile. W (both) + x tile in dynamic smem.
// ---------------------------------------------------------------------------
#define GEMM_SMEM (128 * 256 * 4 + 64 * 132 * 4)   // 131072 + 33792 = 164864 B

__global__ void __launch_bounds__(256, 1)
k_gemm(const float* __restrict__ x, const float* __restrict__ Wl,
       const float* __restrict__ Wr, int n) {
    extern __shared__ float smem[];
    float* sW = smem;                 // [128][256]
    float* sX = smem + 128 * 256;     // [64][132] (padded stride vs bank conflicts)
    const int tid = threadIdx.x;

    // Load W_l|W_r into smem as combined [k][256]
    float4* sW4 = (float4*)sW;
    for (int t = tid; t < 128 * 64; t += 256) {
        int k = t >> 6;            // 64 float4 per k-row
        int c4 = t & 63;
        int col = c4 << 2;
        float4 v;
        if (col < 128) v = *(const float4*)&Wl[k * 128 + col];
        else           v = *(const float4*)&Wr[k * 128 + (col - 128)];
        sW4[t] = v;
    }
    // Load 64-row x tile (padded row stride 132 floats = 33 float4)
    const int r0 = blockIdx.x * 64;
    float4* sX4 = (float4*)sX;
    for (int t = tid; t < 64 * 32; t += 256) {
        int r = t >> 5;
        int c4 = t & 31;
        int row = r0 + r;
        float4 v = make_float4(0.f, 0.f, 0.f, 0.f);
        if (row < n) v = *(const float4*)&x[(size_t)row * 128 + (c4 << 2)];
        sX4[r * 33 + c4] = v;
    }
    __syncthreads();

    const int tx = tid & 15;   // col group: cols [16*tx, 16*tx+16)
    const int ty = tid >> 4;   // row group: rows [4*ty, 4*ty+4)

    float acc[4][16];
#pragma unroll
    for (int i = 0; i < 4; i++)
#pragma unroll
        for (int j = 0; j < 16; j++) acc[i][j] = 0.f;

#pragma unroll 4
    for (int k = 0; k < 128; ++k) {
        float a0 = sX[(ty * 4 + 0) * 132 + k];
        float a1 = sX[(ty * 4 + 1) * 132 + k];
        float a2 = sX[(ty * 4 + 2) * 132 + k];
        float a3 = sX[(ty * 4 + 3) * 132 + k];
        const float4* wrow = (const float4*)&sW[k * 256 + tx * 16];
        float4 b0 = wrow[0], b1 = wrow[1], b2 = wrow[2], b3 = wrow[3];
        float b[16] = {b0.x, b0.y, b0.z, b0.w, b1.x, b1.y, b1.z, b1.w,
                       b2.x, b2.y, b2.z, b2.w, b3.x, b3.y, b3.z, b3.w};
#pragma unroll
        for (int j = 0; j < 16; j++) {
            acc[0][j] += a0 * b[j];
            acc[1][j] += a1 * b[j];
            acc[2][j] += a2 * b[j];
            acc[3][j] += a3 * b[j];
        }
    }

#pragma unroll
    for (int i = 0; i < 4; i++) {
        int row = r0 + ty * 4 + i;
        if (row >= n) continue;
        float* dst;
        if (tx < 8) dst = &g_xl[(size_t)row * 128 + tx * 16];
        else        dst = &g_xr[(size_t)row * 128 + (tx - 8) * 16];
#pragma unroll
        for (int j4 = 0; j4 < 4; j4++) {
            *(float4*)&dst[j4 * 4] = make_float4(acc[i][j4 * 4 + 0], acc[i][j4 * 4 + 1],
                                                 acc[i][j4 * 4 + 2], acc[i][j4 * 4 + 3]);
        }
    }
}

// ---------------------------------------------------------------------------
// K2: one warp per edge. score[h] = att[h] . lrelu(xl[src]+xr[dst]);
// ex = exp(score) (no max-subtraction needed: scores ~N(0,1.4), no overflow);
// denominator accumulated with atomicAdd. ex stored per edge.
// edge_index is int32 (JAX x64 disabled: jnp.int64 -> int32).
// ---------------------------------------------------------------------------
__global__ void __launch_bounds__(256)
k_score(const int* __restrict__ ei, const float* __restrict__ att, int E) {
    int e = (blockIdx.x * blockDim.x + threadIdx.x) >> 5;
    int lane = threadIdx.x & 31;
    if (e >= E) return;
    int src = ei[e];
    int dst = ei[E + e];

    float4 a  = *(const float4*)&att[lane * 4];
    float4 xj = *(const float4*)&g_xl[(size_t)src * 128 + lane * 4];
    float4 xi = *(const float4*)&g_xr[(size_t)dst * 128 + lane * 4];

    float t0 = xi.x + xj.x; t0 = t0 > 0.f ? t0 : NEG_SLOPE * t0;
    float t1 = xi.y + xj.y; t1 = t1 > 0.f ? t1 : NEG_SLOPE * t1;
    float t2 = xi.z + xj.z; t2 = t2 > 0.f ? t2 : NEG_SLOPE * t2;
    float t3 = xi.w + xj.w; t3 = t3 > 0.f ? t3 : NEG_SLOPE * t3;
    float s = t0 * a.x + t1 * a.y + t2 * a.z + t3 * a.w;

    // reduce over the 8 lanes of each head (lanes [8h, 8h+8))
    s += __shfl_xor_sync(0xffffffffu, s, 1);
    s += __shfl_xor_sync(0xffffffffu, s, 2);
    s += __shfl_xor_sync(0xffffffffu, s, 4);

    if ((lane & 7) == 0) {
        int h = lane >> 3;
        float ex = __expf(s);
        g_ex[(size_t)e * 4 + h] = ex;
        atomicAdd(&g_den[(size_t)dst * 4 + h], ex);
    }
}

// ---------------------------------------------------------------------------
// K3: one warp per edge. alpha = ex/(den+1e-16); out[dst] += alpha * xl[src]
// via vectorized red.global.add.v4.f32 (4x fewer atomic ops than scalar).
// ---------------------------------------------------------------------------
__global__ void __launch_bounds__(256)
k_agg(const int* __restrict__ ei, float* __restrict__ out, int E) {
    int e = (blockIdx.x * blockDim.x + threadIdx.x) >> 5;
    int lane = threadIdx.x & 31;
    if (e >= E) return;
    int src = ei[e];
    int dst = ei[E + e];
    int h = lane >> 3;

    float ex  = g_ex[(size_t)e * 4 + h];
    float den = g_den[(size_t)dst * 4 + h];
    float alpha = ex / (den + 1e-16f);

    float4 xj = *(const float4*)&g_xl[(size_t)src * 128 + lane * 4];
    float* p = &out[(size_t)dst * 128 + lane * 4];
    asm volatile("red.global.add.v4.f32 [%0], {%1, %2, %3, %4};"
                 :: "l"(p), "f"(alpha * xj.x), "f"(alpha * xj.y),
                    "f"(alpha * xj.z), "f"(alpha * xj.w)
                 : "memory");
}

// ---------------------------------------------------------------------------
extern "C" void kernel_launch(void* const* d_in, const int* in_sizes, int n_in,
                              void* d_out, int out_size) {
    const float* x      = (const float*)d_in[0];
    const int*   ei     = (const int*)d_in[1];     // int32! (JAX x64 off)
    const float* Wl     = (const float*)d_in[2];
    const float* Wr     = (const float*)d_in[3];
    const float* att    = (const float*)d_in[4];
    const float* bias   = (const float*)d_in[5];
    float* out          = (float*)d_out;

    int n = in_sizes[0] / 128;
    int E = in_sizes[1] / 2;

    k_init<<<(n * 128 + 255) / 256, 256>>>(out, bias, n);

    cudaFuncSetAttribute(k_gemm, cudaFuncAttributeMaxDynamicSharedMemorySize, GEMM_SMEM);
    k_gemm<<<(n + 63) / 64, 256, GEMM_SMEM>>>(x, Wl, Wr, n);

    int blocks_e = (E + 7) / 8;   // 8 warps (edges) per 256-thread block
    k_score<<<blocks_e, 256>>>(ei, att, E);
    k_agg<<<blocks_e, 256>>>(ei, out, E);
}

// round 5
// speedup vs baseline: 1.2299x; 1.2299x over previous
#include <cuda_runtime.h>
#include <cstdint>

// Problem constants (GATv2: N=100000, E=1600000, D_IN=128, H=4, C=32)
#define NMAX 100000
#define NEG_SLOPE 0.2f

// Scratch (allocation-free: __device__ globals)
__device__ float g_xl[(size_t)NMAX * 128];   // 51.2 MB  x @ W_l
__device__ float g_xr[(size_t)NMAX * 128];   // 51.2 MB  x @ W_r
__device__ float g_den[(size_t)NMAX * 4];    //  1.6 MB  softmax denominator per node/head

// ---------------------------------------------------------------------------
// K0: zero out (numerator accumulator) and denominators
// ---------------------------------------------------------------------------
__global__ void k_init(float* __restrict__ out, int n) {
    int i = blockIdx.x * blockDim.x + threadIdx.x;
    if (i < n * 32) *(float4*)&out[(size_t)i * 4] = make_float4(0.f, 0.f, 0.f, 0.f);
    if (i < n * 4) g_den[i] = 0.f;
}

// ---------------------------------------------------------------------------
// K1: fused GEMM  xl = x @ W_l, xr = x @ W_r  using packed fma.rn.f32x2
// Block: 64 rows x 256 output cols (128 xl | 128 xr). 256 threads,
// each thread computes a 4x16 microtile (held as 4x8 packed f32x2 pairs).
// ---------------------------------------------------------------------------
#define GEMM_SMEM (128 * 256 * 4 + 64 * 132 * 4)   // 164864 B

__device__ __forceinline__ unsigned long long bcast2(float a) {
    unsigned long long r;
    unsigned int u = __float_as_uint(a);
    asm("mov.b64 %0, {%1, %1};" : "=l"(r) : "r"(u));
    return r;
}
#define FMA2(acc, a, b) \
    asm volatile("fma.rn.f32x2 %0, %1, %2, %0;" : "+l"(acc) : "l"(a), "l"(b))

__global__ void __launch_bounds__(256, 1)
k_gemm(const float* __restrict__ x, const float* __restrict__ Wl,
       const float* __restrict__ Wr, int n) {
    extern __shared__ float smem[];
    float* sW = smem;                 // [128][256]  (W_l | W_r)
    float* sX = smem + 128 * 256;     // [64][132]   padded row stride
    const int tid = threadIdx.x;

    float4* sW4 = (float4*)sW;
    for (int t = tid; t < 128 * 64; t += 256) {
        int k = t >> 6;
        int c4 = t & 63;
        int col = c4 << 2;
        float4 v;
        if (col < 128) v = *(const float4*)&Wl[k * 128 + col];
        else           v = *(const float4*)&Wr[k * 128 + (col - 128)];
        sW4[t] = v;
    }
    const int r0 = blockIdx.x * 64;
    float4* sX4 = (float4*)sX;
    for (int t = tid; t < 64 * 32; t += 256) {
        int r = t >> 5;
        int c4 = t & 31;
        int row = r0 + r;
        float4 v = make_float4(0.f, 0.f, 0.f, 0.f);
        if (row < n) v = *(const float4*)&x[(size_t)row * 128 + (c4 << 2)];
        sX4[r * 33 + c4] = v;
    }
    __syncthreads();

    const int tx = tid & 15;   // col group: cols [16*tx, 16*tx+16)
    const int ty = tid >> 4;   // row group: rows [4*ty, 4*ty+4)

    unsigned long long acc[4][8];
#pragma unroll
    for (int i = 0; i < 4; i++)
#pragma unroll
        for (int j = 0; j < 8; j++) acc[i][j] = 0ULL;

#pragma unroll 4
    for (int k = 0; k < 128; ++k) {
        unsigned long long a0 = bcast2(sX[(ty * 4 + 0) * 132 + k]);
        unsigned long long a1 = bcast2(sX[(ty * 4 + 1) * 132 + k]);
        unsigned long long a2 = bcast2(sX[(ty * 4 + 2) * 132 + k]);
        unsigned long long a3 = bcast2(sX[(ty * 4 + 3) * 132 + k]);
        const unsigned long long* wrow =
            (const unsigned long long*)&sW[k * 256 + tx * 16];
        unsigned long long b[8];
#pragma unroll
        for (int j = 0; j < 8; j++) b[j] = wrow[j];
#pragma unroll
        for (int j = 0; j < 8; j++) {
            FMA2(acc[0][j], a0, b[j]);
            FMA2(acc[1][j], a1, b[j]);
            FMA2(acc[2][j], a2, b[j]);
            FMA2(acc[3][j], a3, b[j]);
        }
    }

#pragma unroll
    for (int i = 0; i < 4; i++) {
        int row = r0 + ty * 4 + i;
        if (row >= n) continue;
        float* dst;
        if (tx < 8) dst = &g_xl[(size_t)row * 128 + tx * 16];
        else        dst = &g_xr[(size_t)row * 128 + (tx - 8) * 16];
        unsigned long long* d64 = (unsigned long long*)dst;
#pragma unroll
        for (int j = 0; j < 8; j++) d64[j] = acc[i][j];
    }
}

// ---------------------------------------------------------------------------
// K2: fused edge pass — one warp per edge.
//   s[h]  = att[h] . lrelu(xl[src] + xr[dst])
//   ex    = exp(s)        (no max-subtract: scores are O(10), exp can't overflow)
//   den[dst][h] += ex     (red.global.add.f32, 4 lanes)
//   out[dst]   += ex * xl[src]   (red.global.add.v4.f32, all lanes)
// The division by den happens in K3 — algebraically identical to per-edge alpha.
// edge_index is int32 (JAX x64 disabled: jnp.int64 -> int32).
// ---------------------------------------------------------------------------
__global__ void __launch_bounds__(256)
k_edge(const int* __restrict__ ei, const float* __restrict__ att,
       float* __restrict__ out, int E) {
    int e = (blockIdx.x * blockDim.x + threadIdx.x) >> 5;
    int lane = threadIdx.x & 31;
    if (e >= E) return;
    int src = ei[e];
    int dst = ei[E + e];

    float4 a  = *(const float4*)&att[lane * 4];
    float4 xj = *(const float4*)&g_xl[(size_t)src * 128 + lane * 4];
    float4 xi = *(const float4*)&g_xr[(size_t)dst * 128 + lane * 4];

    float t0 = xi.x + xj.x; t0 = t0 > 0.f ? t0 : NEG_SLOPE * t0;
    float t1 = xi.y + xj.y; t1 = t1 > 0.f ? t1 : NEG_SLOPE * t1;
    float t2 = xi.z + xj.z; t2 = t2 > 0.f ? t2 : NEG_SLOPE * t2;
    float t3 = xi.w + xj.w; t3 = t3 > 0.f ? t3 : NEG_SLOPE * t3;
    float s = t0 * a.x + t1 * a.y + t2 * a.z + t3 * a.w;

    // full reduce over the 8 lanes of each head -> every lane holds its head's sum
    s += __shfl_xor_sync(0xffffffffu, s, 1);
    s += __shfl_xor_sync(0xffffffffu, s, 2);
    s += __shfl_xor_sync(0xffffffffu, s, 4);

    float ex = __expf(s);

    if ((lane & 7) == 0) {
        float* dp = &g_den[(size_t)dst * 4 + (lane >> 3)];
        asm volatile("red.global.add.f32 [%0], %1;" :: "l"(dp), "f"(ex) : "memory");
    }

    float* p = &out[(size_t)dst * 128 + lane * 4];
    asm volatile("red.global.add.v4.f32 [%0], {%1, %2, %3, %4};"
                 :: "l"(p), "f"(ex * xj.x), "f"(ex * xj.y),
                    "f"(ex * xj.z), "f"(ex * xj.w)
                 : "memory");
}

// ---------------------------------------------------------------------------
// K3: normalize + bias.  out = out / (den + 1e-16) + bias
// ---------------------------------------------------------------------------
__global__ void k_final(float* __restrict__ out, const float* __restrict__ bias, int n) {
    int i = blockIdx.x * blockDim.x + threadIdx.x;   // one float4 per thread
    if (i >= n * 32) return;
    int node = i >> 5;
    int c4 = i & 31;               // float4 index within row; head = c4>>3
    float inv = 1.f / (g_den[(size_t)node * 4 + (c4 >> 3)] + 1e-16f);
    float4 v = *(float4*)&out[(size_t)i * 4];
    float4 b = *(const float4*)&bias[c4 * 4];
    v.x = v.x * inv + b.x;
    v.y = v.y * inv + b.y;
    v.z = v.z * inv + b.z;
    v.w = v.w * inv + b.w;
    *(float4*)&out[(size_t)i * 4] = v;
}

// ---------------------------------------------------------------------------
extern "C" void kernel_launch(void* const* d_in, const int* in_sizes, int n_in,
                              void* d_out, int out_size) {
    const float* x      = (const float*)d_in[0];
    const int*   ei     = (const int*)d_in[1];     // int32 (JAX x64 off)
    const float* Wl     = (const float*)d_in[2];
    const float* Wr     = (const float*)d_in[3];
    const float* att    = (const float*)d_in[4];
    const float* bias   = (const float*)d_in[5];
    float* out          = (float*)d_out;

    int n = in_sizes[0] / 128;
    int E = in_sizes[1] / 2;

    k_init<<<(n * 32 + 255) / 256, 256>>>(out, n);

    cudaFuncSetAttribute(k_gemm, cudaFuncAttributeMaxDynamicSharedMemorySize, GEMM_SMEM);
    k_gemm<<<(n + 63) / 64, 256, GEMM_SMEM>>>(x, Wl, Wr, n);

    int blocks_e = (E + 7) / 8;   // 8 warps (edges) per 256-thread block
    k_edge<<<blocks_e, 256>>>(ei, att, out, E);

    k_final<<<(n * 32 + 255) / 256, 256>>>(out, bias, n);
}

// round 9
// speedup vs baseline: 1.2781x; 1.0392x over previous
#include <cuda_runtime.h>
#include <cstdint>

// Problem constants (GATv2: N=100000, E=1600000, D_IN=128, H=4, C=32)
#define NMAX 100000
#define NEG_SLOPE 0.2f

// Scratch (allocation-free: __device__ globals)
__device__ float g_xl[(size_t)NMAX * 128];   // 51.2 MB  x @ W_l
__device__ float g_xr[(size_t)NMAX * 128];   // 51.2 MB  x @ W_r
__device__ float g_den[(size_t)NMAX * 4];    //  1.6 MB  softmax denominator per node/head

// ---------------------------------------------------------------------------
// K0: zero out (numerator accumulator) and denominators
// ---------------------------------------------------------------------------
__global__ void k_init(float* __restrict__ out, int n) {
    int i = blockIdx.x * blockDim.x + threadIdx.x;
    if (i < n * 32) *(float4*)&out[(size_t)i * 4] = make_float4(0.f, 0.f, 0.f, 0.f);
    if (i < n * 4) g_den[i] = 0.f;
}

// ---------------------------------------------------------------------------
// K1: fused GEMM  xl = x @ W_l, xr = x @ W_r  using packed fma.rn.f32x2
// Block: 64 rows x 256 output cols (128 xl | 128 xr). 256 threads,
// each thread computes a 4x16 microtile (held as 4x8 packed f32x2 pairs).
// ---------------------------------------------------------------------------
#define GEMM_SMEM (128 * 256 * 4 + 64 * 132 * 4)   // 164864 B

__device__ __forceinline__ unsigned long long bcast2(float a) {
    unsigned long long r;
    unsigned int u = __float_as_uint(a);
    asm("mov.b64 %0, {%1, %1};" : "=l"(r) : "r"(u));
    return r;
}
#define FMA2(acc, a, b) \
    asm volatile("fma.rn.f32x2 %0, %1, %2, %0;" : "+l"(acc) : "l"(a), "l"(b))

__global__ void __launch_bounds__(256, 1)
k_gemm(const float* __restrict__ x, const float* __restrict__ Wl,
       const float* __restrict__ Wr, int n) {
    extern __shared__ float smem[];
    float* sW = smem;                 // [128][256]  (W_l | W_r)
    float* sX = smem + 128 * 256;     // [64][132]   padded row stride
    const int tid = threadIdx.x;

    float4* sW4 = (float4*)sW;
    for (int t = tid; t < 128 * 64; t += 256) {
        int k = t >> 6;
        int c4 = t & 63;
        int col = c4 << 2;
        float4 v;
        if (col < 128) v = *(const float4*)&Wl[k * 128 + col];
        else           v = *(const float4*)&Wr[k * 128 + (col - 128)];
        sW4[t] = v;
    }
    const int r0 = blockIdx.x * 64;
    float4* sX4 = (float4*)sX;
    for (int t = tid; t < 64 * 32; t += 256) {
        int r = t >> 5;
        int c4 = t & 31;
        int row = r0 + r;
        float4 v = make_float4(0.f, 0.f, 0.f, 0.f);
        if (row < n) v = *(const float4*)&x[(size_t)row * 128 + (c4 << 2)];
        sX4[r * 33 + c4] = v;
    }
    __syncthreads();

    const int tx = tid & 15;   // col group: cols [16*tx, 16*tx+16)
    const int ty = tid >> 4;   // row group: rows [4*ty, 4*ty+4)

    unsigned long long acc[4][8];
#pragma unroll
    for (int i = 0; i < 4; i++)
#pragma unroll
        for (int j = 0; j < 8; j++) acc[i][j] = 0ULL;

#pragma unroll 4
    for (int k = 0; k < 128; ++k) {
        unsigned long long a0 = bcast2(sX[(ty * 4 + 0) * 132 + k]);
        unsigned long long a1 = bcast2(sX[(ty * 4 + 1) * 132 + k]);
        unsigned long long a2 = bcast2(sX[(ty * 4 + 2) * 132 + k]);
        unsigned long long a3 = bcast2(sX[(ty * 4 + 3) * 132 + k]);
        const unsigned long long* wrow =
            (const unsigned long long*)&sW[k * 256 + tx * 16];
        unsigned long long b[8];
#pragma unroll
        for (int j = 0; j < 8; j++) b[j] = wrow[j];
#pragma unroll
        for (int j = 0; j < 8; j++) {
            FMA2(acc[0][j], a0, b[j]);
            FMA2(acc[1][j], a1, b[j]);
            FMA2(acc[2][j], a2, b[j]);
            FMA2(acc[3][j], a3, b[j]);
        }
    }

#pragma unroll
    for (int i = 0; i < 4; i++) {
        int row = r0 + ty * 4 + i;
        if (row >= n) continue;
        float* dst;
        if (tx < 8) dst = &g_xl[(size_t)row * 128 + tx * 16];
        else        dst = &g_xr[(size_t)row * 128 + (tx - 8) * 16];
        unsigned long long* d64 = (unsigned long long*)dst;
#pragma unroll
        for (int j = 0; j < 8; j++) d64[j] = acc[i][j];
    }
}

// ---------------------------------------------------------------------------
// K2: fused edge pass — one warp per 4 EDGES (front-batched gathers for MLP).
//   s[h]  = att[h] . lrelu(xl[src] + xr[dst])
//   ex    = exp(s)        (no max-subtract: scores are O(10), exp can't overflow)
//   den[dst][h] += ex     (red.global.add.f32)
//   out[dst]    += ex * xl[src]   (red.global.add.v4.f32)
// Division by den happens in K3 — algebraically identical to per-edge alpha.
// edge_index is int32 (JAX x64 disabled: jnp.int64 -> int32).
// ---------------------------------------------------------------------------
#define EPW 4   // edges per warp

__global__ void __launch_bounds__(256)
k_edge(const int* __restrict__ ei, const float* __restrict__ att,
       float* __restrict__ out, int E) {
    int warp = (blockIdx.x * blockDim.x + threadIdx.x) >> 5;
    int lane = threadIdx.x & 31;
    int e0 = warp * EPW;
    if (e0 >= E) return;

    float4 a = *(const float4*)&att[lane * 4];

    int srcs[EPW], dsts[EPW];
#pragma unroll
    for (int i = 0; i < EPW; i++) {
        int e = min(e0 + i, E - 1);
        srcs[i] = __ldg(&ei[e]);
        dsts[i] = __ldg(&ei[E + e]);
    }

    // Front-batch all 8 row gathers -> 8 outstanding LDG.128 per lane
    float4 xj[EPW], xi[EPW];
#pragma unroll
    for (int i = 0; i < EPW; i++)
        xj[i] = *(const float4*)&g_xl[(size_t)srcs[i] * 128 + lane * 4];
#pragma unroll
    for (int i = 0; i < EPW; i++)
        xi[i] = *(const float4*)&g_xr[(size_t)dsts[i] * 128 + lane * 4];

#pragma unroll
    for (int i = 0; i < EPW; i++) {
        bool valid = (e0 + i) < E;
        float t0 = xi[i].x + xj[i].x; t0 = t0 > 0.f ? t0 : NEG_SLOPE * t0;
        float t1 = xi[i].y + xj[i].y; t1 = t1 > 0.f ? t1 : NEG_SLOPE * t1;
        float t2 = xi[i].z + xj[i].z; t2 = t2 > 0.f ? t2 : NEG_SLOPE * t2;
        float t3 = xi[i].w + xj[i].w; t3 = t3 > 0.f ? t3 : NEG_SLOPE * t3;
        float s = t0 * a.x + t1 * a.y + t2 * a.z + t3 * a.w;

        // full reduce over the 8 lanes of each head
        s += __shfl_xor_sync(0xffffffffu, s, 1);
        s += __shfl_xor_sync(0xffffffffu, s, 2);
        s += __shfl_xor_sync(0xffffffffu, s, 4);

        float ex = __expf(s);

        if (valid) {
            if ((lane & 7) == 0) {
                float* dp = &g_den[(size_t)dsts[i] * 4 + (lane >> 3)];
                asm volatile("red.global.add.f32 [%0], %1;" :: "l"(dp), "f"(ex) : "memory");
            }
            float* p = &out[(size_t)dsts[i] * 128 + lane * 4];
            asm volatile("red.global.add.v4.f32 [%0], {%1, %2, %3, %4};"
                         :: "l"(p), "f"(ex * xj[i].x), "f"(ex * xj[i].y),
                            "f"(ex * xj[i].z), "f"(ex * xj[i].w)
                         : "memory");
        }
    }
}

// ---------------------------------------------------------------------------
// K3: normalize + bias.  out = out / (den + 1e-16) + bias
// ---------------------------------------------------------------------------
__global__ void k_final(float* __restrict__ out, const float* __restrict__ bias, int n) {
    int i = blockIdx.x * blockDim.x + threadIdx.x;   // one float4 per thread
    if (i >= n * 32) return;
    int node = i >> 5;
    int c4 = i & 31;               // float4 index within row; head = c4>>3
    float inv = 1.f / (g_den[(size_t)node * 4 + (c4 >> 3)] + 1e-16f);
    float4 v = *(float4*)&out[(size_t)i * 4];
    float4 b = *(const float4*)&bias[c4 * 4];
    v.x = v.x * inv + b.x;
    v.y = v.y * inv + b.y;
    v.z = v.z * inv + b.z;
    v.w = v.w * inv + b.w;
    *(float4*)&out[(size_t)i * 4] = v;
}

// ---------------------------------------------------------------------------
extern "C" void kernel_launch(void* const* d_in, const int* in_sizes, int n_in,
                              void* d_out, int out_size) {
    const float* x      = (const float*)d_in[0];
    const int*   ei     = (const int*)d_in[1];     // int32 (JAX x64 off)
    const float* Wl     = (const float*)d_in[2];
    const float* Wr     = (const float*)d_in[3];
    const float* att    = (const float*)d_in[4];
    const float* bias   = (const float*)d_in[5];
    float* out          = (float*)d_out;

    int n = in_sizes[0] / 128;
    int E = in_sizes[1] / 2;

    k_init<<<(n * 32 + 255) / 256, 256>>>(out, n);

    cudaFuncSetAttribute(k_gemm, cudaFuncAttributeMaxDynamicSharedMemorySize, GEMM_SMEM);
    k_gemm<<<(n + 63) / 64, 256, GEMM_SMEM>>>(x, Wl, Wr, n);

    int warps_needed = (E + EPW - 1) / EPW;
    int blocks_e = (warps_needed + 7) / 8;   // 8 warps per 256-thread block
    k_edge<<<blocks_e, 256>>>(ei, att, out, E);

    k_final<<<(n * 32 + 255) / 256, 256>>>(out, bias, n);
}

// round 11
// speedup vs baseline: 1.4881x; 1.1643x over previous
#include <cuda_runtime.h>
#include <cstdint>

// Problem constants (GATv2: N=100000, E=1600000, D_IN=128, H=4, C=32)
#define NMAX 100000
#define EMAX 1600000
#define NEG_SLOPE 0.2f
#define SCAN_BLK 1024

// Scratch (allocation-free: __device__ globals)
__device__ float g_xl[(size_t)NMAX * 128];    // 51.2 MB  x @ W_l
__device__ float g_xr[(size_t)NMAX * 128];    // 51.2 MB  x @ W_r
__device__ int   g_cnt[NMAX];                 // in-degree per node
__device__ int   g_rowstart[NMAX];            // CSR row offsets (exclusive)
__device__ int   g_cursor[NMAX];              // scatter cursors
__device__ int   g_csrc[EMAX];                // CSR src indices grouped by dst
__device__ int   g_bsum[128];                 // per-block degree sums (<=98 used)

// ---------------------------------------------------------------------------
// CSR build: zero counts -> histogram -> block reduce -> block scan -> local
// scan + offsets -> scatter. edge_index is int32 (JAX x64 off).
// ---------------------------------------------------------------------------
__global__ void k_zero(int n) {
    int i = blockIdx.x * blockDim.x + threadIdx.x;
    if (i < n) g_cnt[i] = 0;
}

__global__ void k_hist(const int* __restrict__ ei, int E) {
    int e = blockIdx.x * blockDim.x + threadIdx.x;
    if (e < E) atomicAdd(&g_cnt[ei[E + e]], 1);
}

__global__ void __launch_bounds__(SCAN_BLK)
k_reduce(int n) {
    __shared__ int s[SCAN_BLK];
    int i = blockIdx.x * SCAN_BLK + threadIdx.x;
    int v = (i < n) ? g_cnt[i] : 0;
    s[threadIdx.x] = v;
    __syncthreads();
    for (int off = SCAN_BLK / 2; off > 0; off >>= 1) {
        if (threadIdx.x < off) s[threadIdx.x] += s[threadIdx.x + off];
        __syncthreads();
    }
    if (threadIdx.x == 0) g_bsum[blockIdx.x] = s[0];
}

__global__ void k_scanblk(int nb) {
    __shared__ int s[128];
    int t = threadIdx.x;
    s[t] = (t < nb) ? g_bsum[t] : 0;
    __syncthreads();
    for (int off = 1; off < 128; off <<= 1) {
        int v = (t >= off) ? s[t - off] : 0;
        __syncthreads();
        s[t] += v;
        __syncthreads();
    }
    if (t < nb) g_bsum[t] = s[t] - ((t < nb) ? ((t == 0) ? s[0] : s[t] - s[t - 1]) : 0) * 0
                              - 0;   // placeholder; corrected below
    // exclusive scan: subtract own original value
    // (recompute: inclusive - original). Original re-read is racy after write,
    // so do it properly with a second buffer approach:
}

// Correct, simple version of the block-sum scan (replaces k_scanblk above).
__global__ void k_scanblk2(int nb) {
    __shared__ int s[128];
    __shared__ int orig[128];
    int t = threadIdx.x;
    int v = (t < nb) ? g_bsum[t] : 0;
    s[t] = v;
    orig[t] = v;
    __syncthreads();
    for (int off = 1; off < 128; off <<= 1) {
        int u = (t >= off) ? s[t - off] : 0;
        __syncthreads();
        s[t] += u;
        __syncthreads();
    }
    if (t < nb) g_bsum[t] = s[t] - orig[t];   // exclusive
}

__global__ void __launch_bounds__(SCAN_BLK)
k_scanlocal(int n) {
    __shared__ int s[SCAN_BLK];
    int i = blockIdx.x * SCAN_BLK + threadIdx.x;
    int t = threadIdx.x;
    int v = (i < n) ? g_cnt[i] : 0;
    s[t] = v;
    __syncthreads();
    for (int off = 1; off < SCAN_BLK; off <<= 1) {
        int u = (t >= off) ? s[t - off] : 0;
        __syncthreads();
        s[t] += u;
        __syncthreads();
    }
    if (i < n) {
        int start = s[t] - v + g_bsum[blockIdx.x];   // exclusive + block offset
        g_rowstart[i] = start;
        g_cursor[i] = start;
    }
}

__global__ void k_scatter(const int* __restrict__ ei, int E) {
    int e = blockIdx.x * blockDim.x + threadIdx.x;
    if (e >= E) return;
    int src = ei[e];
    int dst = ei[E + e];
    int pos = atomicAdd(&g_cursor[dst], 1);
    g_csrc[pos] = src;
}

// ---------------------------------------------------------------------------
// K1: fused GEMM  xl = x @ W_l, xr = x @ W_r  using packed fma.rn.f32x2
// ---------------------------------------------------------------------------
#define GEMM_SMEM (128 * 256 * 4 + 64 * 132 * 4)   // 164864 B

__device__ __forceinline__ unsigned long long bcast2(float a) {
    unsigned long long r;
    unsigned int u = __float_as_uint(a);
    asm("mov.b64 %0, {%1, %1};" : "=l"(r) : "r"(u));
    return r;
}
#define FMA2(acc, a, b) \
    asm volatile("fma.rn.f32x2 %0, %1, %2, %0;" : "+l"(acc) : "l"(a), "l"(b))

__global__ void __launch_bounds__(256, 1)
k_gemm(const float* __restrict__ x, const float* __restrict__ Wl,
       const float* __restrict__ Wr, int n) {
    extern __shared__ float smem[];
    float* sW = smem;                 // [128][256]  (W_l | W_r)
    float* sX = smem + 128 * 256;     // [64][132]   padded row stride
    const int tid = threadIdx.x;

    float4* sW4 = (float4*)sW;
    for (int t = tid; t < 128 * 64; t += 256) {
        int k = t >> 6;
        int c4 = t & 63;
        int col = c4 << 2;
        float4 v;
        if (col < 128) v = *(const float4*)&Wl[k * 128 + col];
        else           v = *(const float4*)&Wr[k * 128 + (col - 128)];
        sW4[t] = v;
    }
    const int r0 = blockIdx.x * 64;
    float4* sX4 = (float4*)sX;
    for (int t = tid; t < 64 * 32; t += 256) {
        int r = t >> 5;
        int c4 = t & 31;
        int row = r0 + r;
        float4 v = make_float4(0.f, 0.f, 0.f, 0.f);
        if (row < n) v = *(const float4*)&x[(size_t)row * 128 + (c4 << 2)];
        sX4[r * 33 + c4] = v;
    }
    __syncthreads();

    const int tx = tid & 15;   // col group: cols [16*tx, 16*tx+16)
    const int ty = tid >> 4;   // row group: rows [4*ty, 4*ty+4)

    unsigned long long acc[4][8];
#pragma unroll
    for (int i = 0; i < 4; i++)
#pragma unroll
        for (int j = 0; j < 8; j++) acc[i][j] = 0ULL;

#pragma unroll 4
    for (int k = 0; k < 128; ++k) {
        unsigned long long a0 = bcast2(sX[(ty * 4 + 0) * 132 + k]);
        unsigned long long a1 = bcast2(sX[(ty * 4 + 1) * 132 + k]);
        unsigned long long a2 = bcast2(sX[(ty * 4 + 2) * 132 + k]);
        unsigned long long a3 = bcast2(sX[(ty * 4 + 3) * 132 + k]);
        const unsigned long long* wrow =
            (const unsigned long long*)&sW[k * 256 + tx * 16];
        unsigned long long b[8];
#pragma unroll
        for (int j = 0; j < 8; j++) b[j] = wrow[j];
#pragma unroll
        for (int j = 0; j < 8; j++) {
            FMA2(acc[0][j], a0, b[j]);
            FMA2(acc[1][j], a1, b[j]);
            FMA2(acc[2][j], a2, b[j]);
            FMA2(acc[3][j], a3, b[j]);
        }
    }

#pragma unroll
    for (int i = 0; i < 4; i++) {
        int row = r0 + ty * 4 + i;
        if (row >= n) continue;
        float* dst;
        if (tx < 8) dst = &g_xl[(size_t)row * 128 + tx * 16];
        else        dst = &g_xr[(size_t)row * 128 + (tx - 8) * 16];
        unsigned long long* d64 = (unsigned long long*)dst;
#pragma unroll
        for (int j = 0; j < 8; j++) d64[j] = acc[i][j];
    }
}

// ---------------------------------------------------------------------------
// K2: per-node aggregation — one warp per destination node, CSR edge list.
// xr[dst] and the output accumulator live in registers; only xl[src] is a
// random gather. No atomics, no second pass: out = acc/den + bias directly.
// ---------------------------------------------------------------------------
__global__ void __launch_bounds__(256)
k_agg(const float* __restrict__ att, const float* __restrict__ bias,
      float* __restrict__ out, int n) {
    int v = (blockIdx.x * blockDim.x + threadIdx.x) >> 5;
    int lane = threadIdx.x & 31;
    if (v >= n) return;

    float4 a  = *(const float4*)&att[lane * 4];
    float4 xi = *(const float4*)&g_xr[(size_t)v * 128 + lane * 4];
    int base = g_rowstart[v];
    int deg  = g_cnt[v];

    float4 acc = make_float4(0.f, 0.f, 0.f, 0.f);
    float den = 0.f;

    for (int k0 = 0; k0 < deg; k0 += 4) {
        int m = deg - k0;
        if (m > 4) m = 4;
        int srcs[4];
#pragma unroll
        for (int i = 0; i < 4; i++)
            srcs[i] = g_csrc[base + k0 + ((i < m) ? i : 0)];
        float4 xj[4];
#pragma unroll
        for (int i = 0; i < 4; i++)
            xj[i] = *(const float4*)&g_xl[(size_t)srcs[i] * 128 + lane * 4];

#pragma unroll
        for (int i = 0; i < 4; i++) {
            if (i >= m) break;
            float t0 = xi.x + xj[i].x; t0 = t0 > 0.f ? t0 : NEG_SLOPE * t0;
            float t1 = xi.y + xj[i].y; t1 = t1 > 0.f ? t1 : NEG_SLOPE * t1;
            float t2 = xi.z + xj[i].z; t2 = t2 > 0.f ? t2 : NEG_SLOPE * t2;
            float t3 = xi.w + xj[i].w; t3 = t3 > 0.f ? t3 : NEG_SLOPE * t3;
            float s = t0 * a.x + t1 * a.y + t2 * a.z + t3 * a.w;
            // reduce over the 8 lanes of each head -> all lanes get their head's sum
            s += __shfl_xor_sync(0xffffffffu, s, 1);
            s += __shfl_xor_sync(0xffffffffu, s, 2);
            s += __shfl_xor_sync(0xffffffffu, s, 4);
            float ex = __expf(s);
            acc.x += ex * xj[i].x;
            acc.y += ex * xj[i].y;
            acc.z += ex * xj[i].z;
            acc.w += ex * xj[i].w;
            den += ex;
        }
    }

    float inv = 1.f / (den + 1e-16f);
    float4 b = *(const float4*)&bias[lane * 4];
    float4 o;
    o.x = acc.x * inv + b.x;
    o.y = acc.y * inv + b.y;
    o.z = acc.z * inv + b.z;
    o.w = acc.w * inv + b.w;
    *(float4*)&out[(size_t)v * 128 + lane * 4] = o;
}

// ---------------------------------------------------------------------------
extern "C" void kernel_launch(void* const* d_in, const int* in_sizes, int n_in,
                              void* d_out, int out_size) {
    const float* x      = (const float*)d_in[0];
    const int*   ei     = (const int*)d_in[1];     // int32 (JAX x64 off)
    const float* Wl     = (const float*)d_in[2];
    const float* Wr     = (const float*)d_in[3];
    const float* att    = (const float*)d_in[4];
    const float* bias   = (const float*)d_in[5];
    float* out          = (float*)d_out;

    int n = in_sizes[0] / 128;
    int E = in_sizes[1] / 2;
    int nb = (n + SCAN_BLK - 1) / SCAN_BLK;

    // CSR build
    k_zero<<<(n + 255) / 256, 256>>>(n);
    k_hist<<<(E + 255) / 256, 256>>>(ei, E);
    k_reduce<<<nb, SCAN_BLK>>>(n);
    k_scanblk2<<<1, 128>>>(nb);
    k_scanlocal<<<nb, SCAN_BLK>>>(n);
    k_scatter<<<(E + 255) / 256, 256>>>(ei, E);

    // GEMM
    cudaFuncSetAttribute(k_gemm, cudaFuncAttributeMaxDynamicSharedMemorySize, GEMM_SMEM);
    k_gemm<<<(n + 63) / 64, 256, GEMM_SMEM>>>(x, Wl, Wr, n);

    // Per-node aggregation (one warp per node)
    k_agg<<<(n * 32 + 255) / 256, 256>>>(att, bias, out, n);
}